// round 15
// baseline (speedup 1.0000x reference)
// mma.sync fp16 fused GEMM+epilogue, v12 = v11 (barrier-free mbarrier pipeline,
// TMA, 64x32 warps, 2 CTAs/SM, producer=warp7) with:
//  (1) early stage-release: last k-step's fragments are loaded to registers,
//      the warp arrives on empty[stage], THEN runs the MMAs -> stage freed one
//      k-step earlier each chunk, producer refills sooner;
//  (2) prep kernel at 16 floats/thread (MLP 4) to approach the HBM ceiling.
//   out = relu(1 - beta + X@W^T); res = relu(1 - beta_res + x + out); leaky==id.

#include <cuda_runtime.h>
#include <cuda.h>
#include <cuda_fp16.h>
#include <cstdint>

#define DIM     4096
#define BM      128
#define BN      128
#define BK      64
#define STAGES  3
#define NT      256
#define NC      (DIM / BK)
#define AB_TILE (BM * BK * 2)
#define STAGE_BYTES (2 * AB_TILE)
#define SMEM_MAIN   (STAGES * STAGE_BYTES)
#define SMEM_TOTAL  (SMEM_MAIN + 64)       // full[0..2] @ +0, empty[0..2] @ +24

// ------------------------------------------------------------------ scratch
__device__ __half g_Xh[(size_t)DIM * DIM];
__device__ __half g_Wh[(size_t)DIM * DIM];

// ------------------------------------------------------------------ helpers
__device__ __forceinline__ uint32_t smem_u32(const void* p) {
    uint32_t a;
    asm("{ .reg .u64 t; cvta.to.shared.u64 t, %1; cvt.u32.u64 %0, t; }" : "=r"(a) : "l"(p));
    return a;
}
__device__ __forceinline__ void mbar_init(uint32_t m, uint32_t cnt) {
    asm volatile("mbarrier.init.shared.b64 [%0], %1;" :: "r"(m), "r"(cnt) : "memory");
}
__device__ __forceinline__ void mbar_arrive(uint32_t m) {
    asm volatile("mbarrier.arrive.shared.b64 _, [%0];" :: "r"(m) : "memory");
}
__device__ __forceinline__ void mbar_expect_tx(uint32_t m, uint32_t bytes) {
    asm volatile("mbarrier.arrive.expect_tx.shared.b64 _, [%0], %1;"
                 :: "r"(m), "r"(bytes) : "memory");
}
__device__ __forceinline__ void mbar_wait(uint32_t m, uint32_t parity) {
    asm volatile(
        "{\n\t.reg .pred P;\n\t"
        "WL_%=:\n\t"
        "mbarrier.try_wait.parity.acquire.cta.shared::cta.b64 P, [%0], %1, 0x989680;\n\t"
        "@!P bra.uni WL_%=;\n\t}"
        :: "r"(m), "r"(parity) : "memory");
}
__device__ __forceinline__ void fence_async() {
    asm volatile("fence.proxy.async.shared::cta;" ::: "memory");
}
__device__ __forceinline__ void tma2d(uint32_t dst, const CUtensorMap* map,
                                      int x, int y, uint32_t bar) {
    asm volatile(
        "cp.async.bulk.tensor.2d.shared::cta.global.tile.mbarrier::complete_tx::bytes "
        "[%0], [%1, {%2, %3}], [%4];"
        :: "r"(dst), "l"(map), "r"(x), "r"(y), "r"(bar) : "memory");
}
__device__ __forceinline__ void ldsm4(uint32_t* r, uint32_t addr) {
    asm volatile("ldmatrix.sync.aligned.m8n8.x4.shared.b16 {%0,%1,%2,%3}, [%4];"
                 : "=r"(r[0]), "=r"(r[1]), "=r"(r[2]), "=r"(r[3]) : "r"(addr));
}
__device__ __forceinline__ void mma_f16(float* d, const uint32_t* a, const uint32_t* b) {
    asm volatile(
        "mma.sync.aligned.m16n8k16.row.col.f32.f16.f16.f32 "
        "{%0,%1,%2,%3}, {%4,%5,%6,%7}, {%8,%9}, {%0,%1,%2,%3};"
        : "+f"(d[0]), "+f"(d[1]), "+f"(d[2]), "+f"(d[3])
        : "r"(a[0]), "r"(a[1]), "r"(a[2]), "r"(a[3]), "r"(b[0]), "r"(b[1]));
}

// ------------------------------------------------------------------ prep kernel
// 16 floats -> 16 halves per thread (MLP 4).
__global__ void __launch_bounds__(256) to_half2_kernel(const float* __restrict__ x,
                                                       const float* __restrict__ w,
                                                       __half* __restrict__ xh,
                                                       __half* __restrict__ wh) {
    const float* in  = blockIdx.y ? w : x;
    __half* outp     = blockIdx.y ? wh : xh;
    size_t i = ((size_t)blockIdx.x * blockDim.x + threadIdx.x) * 16;
    float4 v0 = __ldcs(reinterpret_cast<const float4*>(in + i));
    float4 v1 = __ldcs(reinterpret_cast<const float4*>(in + i + 4));
    float4 v2 = __ldcs(reinterpret_cast<const float4*>(in + i + 8));
    float4 v3 = __ldcs(reinterpret_cast<const float4*>(in + i + 12));
    __half2 h0 = __floats2half2_rn(v0.x, v0.y);
    __half2 h1 = __floats2half2_rn(v0.z, v0.w);
    __half2 h2 = __floats2half2_rn(v1.x, v1.y);
    __half2 h3 = __floats2half2_rn(v1.z, v1.w);
    __half2 h4 = __floats2half2_rn(v2.x, v2.y);
    __half2 h5 = __floats2half2_rn(v2.z, v2.w);
    __half2 h6 = __floats2half2_rn(v3.x, v3.y);
    __half2 h7 = __floats2half2_rn(v3.z, v3.w);
    uint4 o0, o1;
    o0.x = *reinterpret_cast<uint32_t*>(&h0);
    o0.y = *reinterpret_cast<uint32_t*>(&h1);
    o0.z = *reinterpret_cast<uint32_t*>(&h2);
    o0.w = *reinterpret_cast<uint32_t*>(&h3);
    o1.x = *reinterpret_cast<uint32_t*>(&h4);
    o1.y = *reinterpret_cast<uint32_t*>(&h5);
    o1.z = *reinterpret_cast<uint32_t*>(&h6);
    o1.w = *reinterpret_cast<uint32_t*>(&h7);
    *reinterpret_cast<uint4*>(outp + i)     = o0;
    *reinterpret_cast<uint4*>(outp + i + 8) = o1;
}

// ------------------------------------------------------------------ main kernel
__global__ void __launch_bounds__(NT, 2)
resfc_mma_f16_v12(const __grid_constant__ CUtensorMap tmaA,
                  const __grid_constant__ CUtensorMap tmaB,
                  const __half* __restrict__ Xh,
                  const float* __restrict__ beta,
                  const float* __restrict__ beta_res,
                  float* __restrict__ out)
{
    extern __shared__ __align__(1024) char smem[];
    const uint32_t sbase = smem_u32(smem);
    const uint32_t fullb0  = sbase + SMEM_MAIN;
    const uint32_t emptyb0 = sbase + SMEM_MAIN + 24;
    const int tid = threadIdx.x;
    const int l   = tid & 31;
    const int wid = tid >> 5;
    const int warpM = (wid & 1) * 64;
    const int warpN = (wid >> 1) * 32;
    const int bm = blockIdx.y * BM;
    const int bn = blockIdx.x * BN;

    if (tid == 0) {
        #pragma unroll
        for (int s = 0; s < STAGES; ++s) {
            mbar_init(fullb0  + 8 * s, 1);
            mbar_init(emptyb0 + 8 * s, 8);
        }
    }
    __syncthreads();

    if (tid == 0) {
        #pragma unroll
        for (int s = 0; s < STAGES; ++s) {
            mbar_expect_tx(fullb0 + 8 * s, STAGE_BYTES);
            tma2d(sbase + s * STAGE_BYTES,           &tmaA, s * BK, bm, fullb0 + 8 * s);
            tma2d(sbase + s * STAGE_BYTES + AB_TILE, &tmaB, s * BK, bn, fullb0 + 8 * s);
        }
    }

    const uint32_t xorv   = (uint32_t)(l & 7) << 4;
    const uint32_t aRow   = (uint32_t)(warpM + (l & 15));
    const uint32_t aByteH = (uint32_t)(l & 16);
    const uint32_t bRow   = (uint32_t)(warpN + (l & 7) + ((l >> 1) & 8));
    const uint32_t bByteH = (uint32_t)((l & 8) << 1);

    float acc[4][4][4];
    #pragma unroll
    for (int i = 0; i < 4; ++i)
        #pragma unroll
        for (int j = 0; j < 4; ++j)
            #pragma unroll
            for (int k = 0; k < 4; ++k)
                acc[i][j][k] = 0.0f;

    #define LOADF(s, aF, bF) do {                                             \
        const uint32_t aoff = ((uint32_t)((s) * 32) + aByteH) ^ xorv;         \
        const uint32_t boff = ((uint32_t)((s) * 32) + bByteH) ^ xorv;         \
        _Pragma("unroll")                                                     \
        for (int t_ = 0; t_ < 4; ++t_)                                        \
            ldsm4((aF)[t_], aBase + (uint32_t)t_ * 2048 + aoff);              \
        _Pragma("unroll")                                                     \
        for (int u_ = 0; u_ < 2; ++u_) {                                      \
            uint32_t r_[4];                                                   \
            ldsm4(r_, bBase + (uint32_t)u_ * 2048 + boff);                    \
            (bF)[2 * u_][0]     = r_[0];  (bF)[2 * u_][1]     = r_[1];        \
            (bF)[2 * u_ + 1][0] = r_[2];  (bF)[2 * u_ + 1][1] = r_[3];        \
        }                                                                     \
    } while (0)

    #define MMAS(aF, bF) do {                                                 \
        _Pragma("unroll")                                                     \
        for (int mt_ = 0; mt_ < 4; ++mt_)                                     \
            _Pragma("unroll")                                                 \
            for (int nt_ = 0; nt_ < 4; ++nt_)                                 \
                mma_f16(acc[mt_][nt_], (aF)[mt_], (bF)[nt_]);                 \
    } while (0)

    mbar_wait(fullb0, 0);
    unsigned phbits = 1u;
    unsigned eph    = 0u;
    int stage = 0;

    for (int c = 0; c < NC; ++c) {
        const uint32_t aBase = sbase + (uint32_t)stage * STAGE_BYTES + aRow * 128;
        const uint32_t bBase = sbase + (uint32_t)stage * STAGE_BYTES + AB_TILE + bRow * 128;

        { uint32_t aF[4][4], bF[4][2]; LOADF(0, aF, bF); MMAS(aF, bF); }
        { uint32_t aF[4][4], bF[4][2]; LOADF(1, aF, bF); MMAS(aF, bF); }
        { uint32_t aF[4][4], bF[4][2]; LOADF(2, aF, bF); MMAS(aF, bF); }

        int snext = stage + 1; if (snext == STAGES) snext = 0;
        if (c + 1 < NC) {
            mbar_wait(fullb0 + 8 * snext, (phbits >> snext) & 1u);
            phbits ^= (1u << snext);
        }

        // k-step 3: load fragments -> release stage -> compute
        {
            uint32_t aF[4][4], bF[4][2];
            LOADF(3, aF, bF);
            __syncwarp();                         // all lanes' LDSMs done
            if (l == 0) mbar_arrive(emptyb0 + 8 * stage);
            MMAS(aF, bF);
        }

        // producer = warp 7 lane 0: refill this stage with chunk c+3
        if (tid == 224) {
            const int cn = c + STAGES;
            if (cn < NC) {
                mbar_wait(emptyb0 + 8 * stage, (eph >> stage) & 1u);
                eph ^= (1u << stage);
                fence_async();
                mbar_expect_tx(fullb0 + 8 * stage, STAGE_BYTES);
                tma2d(sbase + stage * STAGE_BYTES,           &tmaA, cn * BK, bm, fullb0 + 8 * stage);
                tma2d(sbase + stage * STAGE_BYTES + AB_TILE, &tmaB, cn * BK, bn, fullb0 + 8 * stage);
            }
        }

        stage = snext;
    }
    #undef LOADF
    #undef MMAS

    // -------- fused epilogue (residual from fp16 Xh; evict-first stores) -----
    const float one_mb = 1.0f - beta[0];
    const int colB = bn + warpN + 2 * (l & 3);

    float2 br2[4];
    #pragma unroll
    for (int nt = 0; nt < 4; ++nt)
        br2[nt] = *reinterpret_cast<const float2*>(beta_res + colB + nt * 8);

    #pragma unroll
    for (int mt = 0; mt < 4; ++mt) {
        #pragma unroll
        for (int h = 0; h < 2; ++h) {
            const int row = bm + warpM + mt * 16 + (l >> 2) + h * 8;
            const __half* xr = Xh  + (size_t)row * DIM + colB;
            float*       orw = out + (size_t)row * DIM + colB;
            #pragma unroll
            for (int nt = 0; nt < 4; ++nt) {
                const __half2 xh2 = *reinterpret_cast<const __half2*>(xr + nt * 8);
                const float2 xv = __half22float2(xh2);
                const float d0 = acc[mt][nt][h * 2 + 0];
                const float d1 = acc[mt][nt][h * 2 + 1];
                const float o0 = fmaxf(one_mb + d0, 0.0f);
                const float o1 = fmaxf(one_mb + d1, 0.0f);
                const float r0 = fmaxf(1.0f - (br2[nt].x - (xv.x + o0)), 0.0f);
                const float r1 = fmaxf(1.0f - (br2[nt].y - (xv.y + o1)), 0.0f);
                __stcs(reinterpret_cast<float2*>(orw + nt * 8), make_float2(r0, r1));
            }
        }
    }
}

// ------------------------------------------------------------------ host side
typedef CUresult (*EncodeTiledFn)(CUtensorMap*, CUtensorMapDataType, cuuint32_t, void*,
                                  const cuuint64_t*, const cuuint64_t*, const cuuint32_t*,
                                  const cuuint32_t*, CUtensorMapInterleave, CUtensorMapSwizzle,
                                  CUtensorMapL2promotion, CUtensorMapFloatOOBfill);

static void make_map(EncodeTiledFn enc, CUtensorMap* m, void* ptr) {
    cuuint64_t dims[2]    = {DIM, DIM};
    cuuint64_t strides[1] = {(cuuint64_t)DIM * 2};
    cuuint32_t box[2]     = {BK, 128};
    cuuint32_t es[2]      = {1, 1};
    enc(m, CU_TENSOR_MAP_DATA_TYPE_FLOAT16, 2, ptr, dims, strides, box, es,
        CU_TENSOR_MAP_INTERLEAVE_NONE, CU_TENSOR_MAP_SWIZZLE_128B,
        CU_TENSOR_MAP_L2_PROMOTION_L2_256B, CU_TENSOR_MAP_FLOAT_OOB_FILL_NONE);
}

extern "C" void kernel_launch(void* const* d_in, const int* in_sizes, int n_in,
                              void* d_out, int out_size)
{
    const float* X        = (const float*)d_in[0];
    const float* W        = (const float*)d_in[1];
    const float* beta     = (const float*)d_in[2];
    const float* beta_res = (const float*)d_in[3];
    float* out            = (float*)d_out;

    void *pXh = nullptr, *pWh = nullptr;
    cudaGetSymbolAddress(&pXh, g_Xh);
    cudaGetSymbolAddress(&pWh, g_Wh);

    dim3 pgrid(DIM * DIM / (256 * 16), 2);
    to_half2_kernel<<<pgrid, 256>>>(X, W, (__half*)pXh, (__half*)pWh);

    void* encp = nullptr;
    cudaDriverEntryPointQueryResult st;
    cudaGetDriverEntryPointByVersion("cuTensorMapEncodeTiled", &encp, 12000,
                                     cudaEnableDefault, &st);
    EncodeTiledFn enc = (EncodeTiledFn)encp;

    static CUtensorMap mapA, mapB;
    make_map(enc, &mapA, pXh);
    make_map(enc, &mapB, pWh);

    cudaFuncSetAttribute(resfc_mma_f16_v12,
                         cudaFuncAttributeMaxDynamicSharedMemorySize, SMEM_TOTAL);
    dim3 grid(DIM / BN, DIM / BM);
    resfc_mma_f16_v12<<<grid, NT, SMEM_TOTAL>>>(mapA, mapB, (const __half*)pXh,
                                                beta, beta_res, out);
}

// round 16
// speedup vs baseline: 1.0055x; 1.0055x over previous
// mma.sync fp16 fused GEMM+epilogue, v13 = measured-best recombination:
//   mainloop  = v11 exactly (barrier-free mbarrier pipeline, TMA loads, 64x32
//               warp tiles, 2 CTAs/SM, producer=warp7, evict-first stores)
//               -> best measured main kernel: 273.0us, tensor 82.5%
//   prep      = v12's 16-floats/thread (MLP 4) converter -> -1.7us measured
// R15 attribution: v12's early stage-release LOST 3.8us in-main (reverted);
// its prep change WON 1.7us (kept).
//   out = relu(1 - beta + X@W^T); res = relu(1 - beta_res + x + out); leaky==id.

#include <cuda_runtime.h>
#include <cuda.h>
#include <cuda_fp16.h>
#include <cstdint>

#define DIM     4096
#define BM      128
#define BN      128
#define BK      64
#define STAGES  3
#define NT      256
#define NC      (DIM / BK)
#define AB_TILE (BM * BK * 2)
#define STAGE_BYTES (2 * AB_TILE)
#define SMEM_MAIN   (STAGES * STAGE_BYTES)
#define SMEM_TOTAL  (SMEM_MAIN + 64)       // full[0..2] @ +0, empty[0..2] @ +24

// ------------------------------------------------------------------ scratch
__device__ __half g_Xh[(size_t)DIM * DIM];
__device__ __half g_Wh[(size_t)DIM * DIM];

// ------------------------------------------------------------------ helpers
__device__ __forceinline__ uint32_t smem_u32(const void* p) {
    uint32_t a;
    asm("{ .reg .u64 t; cvta.to.shared.u64 t, %1; cvt.u32.u64 %0, t; }" : "=r"(a) : "l"(p));
    return a;
}
__device__ __forceinline__ void mbar_init(uint32_t m, uint32_t cnt) {
    asm volatile("mbarrier.init.shared.b64 [%0], %1;" :: "r"(m), "r"(cnt) : "memory");
}
__device__ __forceinline__ void mbar_arrive(uint32_t m) {
    asm volatile("mbarrier.arrive.shared.b64 _, [%0];" :: "r"(m) : "memory");
}
__device__ __forceinline__ void mbar_expect_tx(uint32_t m, uint32_t bytes) {
    asm volatile("mbarrier.arrive.expect_tx.shared.b64 _, [%0], %1;"
                 :: "r"(m), "r"(bytes) : "memory");
}
__device__ __forceinline__ void mbar_wait(uint32_t m, uint32_t parity) {
    asm volatile(
        "{\n\t.reg .pred P;\n\t"
        "WL_%=:\n\t"
        "mbarrier.try_wait.parity.acquire.cta.shared::cta.b64 P, [%0], %1, 0x989680;\n\t"
        "@!P bra.uni WL_%=;\n\t}"
        :: "r"(m), "r"(parity) : "memory");
}
__device__ __forceinline__ void fence_async() {
    asm volatile("fence.proxy.async.shared::cta;" ::: "memory");
}
__device__ __forceinline__ void tma2d(uint32_t dst, const CUtensorMap* map,
                                      int x, int y, uint32_t bar) {
    asm volatile(
        "cp.async.bulk.tensor.2d.shared::cta.global.tile.mbarrier::complete_tx::bytes "
        "[%0], [%1, {%2, %3}], [%4];"
        :: "r"(dst), "l"(map), "r"(x), "r"(y), "r"(bar) : "memory");
}
__device__ __forceinline__ void ldsm4(uint32_t* r, uint32_t addr) {
    asm volatile("ldmatrix.sync.aligned.m8n8.x4.shared.b16 {%0,%1,%2,%3}, [%4];"
                 : "=r"(r[0]), "=r"(r[1]), "=r"(r[2]), "=r"(r[3]) : "r"(addr));
}
__device__ __forceinline__ void mma_f16(float* d, const uint32_t* a, const uint32_t* b) {
    asm volatile(
        "mma.sync.aligned.m16n8k16.row.col.f32.f16.f16.f32 "
        "{%0,%1,%2,%3}, {%4,%5,%6,%7}, {%8,%9}, {%0,%1,%2,%3};"
        : "+f"(d[0]), "+f"(d[1]), "+f"(d[2]), "+f"(d[3])
        : "r"(a[0]), "r"(a[1]), "r"(a[2]), "r"(a[3]), "r"(b[0]), "r"(b[1]));
}

// ------------------------------------------------------------------ prep kernel
// 16 floats -> 16 halves per thread (MLP 4) — measured -1.7us vs 8/thread.
__global__ void __launch_bounds__(256) to_half2_kernel(const float* __restrict__ x,
                                                       const float* __restrict__ w,
                                                       __half* __restrict__ xh,
                                                       __half* __restrict__ wh) {
    const float* in  = blockIdx.y ? w : x;
    __half* outp     = blockIdx.y ? wh : xh;
    size_t i = ((size_t)blockIdx.x * blockDim.x + threadIdx.x) * 16;
    float4 v0 = __ldcs(reinterpret_cast<const float4*>(in + i));
    float4 v1 = __ldcs(reinterpret_cast<const float4*>(in + i + 4));
    float4 v2 = __ldcs(reinterpret_cast<const float4*>(in + i + 8));
    float4 v3 = __ldcs(reinterpret_cast<const float4*>(in + i + 12));
    __half2 h0 = __floats2half2_rn(v0.x, v0.y);
    __half2 h1 = __floats2half2_rn(v0.z, v0.w);
    __half2 h2 = __floats2half2_rn(v1.x, v1.y);
    __half2 h3 = __floats2half2_rn(v1.z, v1.w);
    __half2 h4 = __floats2half2_rn(v2.x, v2.y);
    __half2 h5 = __floats2half2_rn(v2.z, v2.w);
    __half2 h6 = __floats2half2_rn(v3.x, v3.y);
    __half2 h7 = __floats2half2_rn(v3.z, v3.w);
    uint4 o0, o1;
    o0.x = *reinterpret_cast<uint32_t*>(&h0);
    o0.y = *reinterpret_cast<uint32_t*>(&h1);
    o0.z = *reinterpret_cast<uint32_t*>(&h2);
    o0.w = *reinterpret_cast<uint32_t*>(&h3);
    o1.x = *reinterpret_cast<uint32_t*>(&h4);
    o1.y = *reinterpret_cast<uint32_t*>(&h5);
    o1.z = *reinterpret_cast<uint32_t*>(&h6);
    o1.w = *reinterpret_cast<uint32_t*>(&h7);
    *reinterpret_cast<uint4*>(outp + i)     = o0;
    *reinterpret_cast<uint4*>(outp + i + 8) = o1;
}

// ------------------------------------------------------------------ main kernel (v11 verbatim)
__global__ void __launch_bounds__(NT, 2)
resfc_mma_f16_v13(const __grid_constant__ CUtensorMap tmaA,
                  const __grid_constant__ CUtensorMap tmaB,
                  const __half* __restrict__ Xh,
                  const float* __restrict__ beta,
                  const float* __restrict__ beta_res,
                  float* __restrict__ out)
{
    extern __shared__ __align__(1024) char smem[];
    const uint32_t sbase = smem_u32(smem);
    const uint32_t fullb0  = sbase + SMEM_MAIN;
    const uint32_t emptyb0 = sbase + SMEM_MAIN + 24;
    const int tid = threadIdx.x;
    const int l   = tid & 31;
    const int wid = tid >> 5;
    const int warpM = (wid & 1) * 64;
    const int warpN = (wid >> 1) * 32;
    const int bm = blockIdx.y * BM;
    const int bn = blockIdx.x * BN;

    if (tid == 0) {
        #pragma unroll
        for (int s = 0; s < STAGES; ++s) {
            mbar_init(fullb0  + 8 * s, 1);
            mbar_init(emptyb0 + 8 * s, 8);
        }
    }
    __syncthreads();

    // prologue: chunks 0,1,2 -> stages 0,1,2
    if (tid == 0) {
        #pragma unroll
        for (int s = 0; s < STAGES; ++s) {
            mbar_expect_tx(fullb0 + 8 * s, STAGE_BYTES);
            tma2d(sbase + s * STAGE_BYTES,           &tmaA, s * BK, bm, fullb0 + 8 * s);
            tma2d(sbase + s * STAGE_BYTES + AB_TILE, &tmaB, s * BK, bn, fullb0 + 8 * s);
        }
    }

    const uint32_t xorv   = (uint32_t)(l & 7) << 4;
    const uint32_t aRow   = (uint32_t)(warpM + (l & 15));
    const uint32_t aByteH = (uint32_t)(l & 16);
    const uint32_t bRow   = (uint32_t)(warpN + (l & 7) + ((l >> 1) & 8));
    const uint32_t bByteH = (uint32_t)((l & 8) << 1);

    float acc[4][4][4];
    #pragma unroll
    for (int i = 0; i < 4; ++i)
        #pragma unroll
        for (int j = 0; j < 4; ++j)
            #pragma unroll
            for (int k = 0; k < 4; ++k)
                acc[i][j][k] = 0.0f;

    #define KSTEP(s) do {                                                     \
        uint32_t aF[4][4];                                                    \
        uint32_t bF[4][2];                                                    \
        const uint32_t aoff = ((uint32_t)((s) * 32) + aByteH) ^ xorv;         \
        const uint32_t boff = ((uint32_t)((s) * 32) + bByteH) ^ xorv;         \
        _Pragma("unroll")                                                     \
        for (int t_ = 0; t_ < 4; ++t_)                                        \
            ldsm4(aF[t_], aBase + (uint32_t)t_ * 2048 + aoff);                \
        _Pragma("unroll")                                                     \
        for (int u_ = 0; u_ < 2; ++u_) {                                      \
            uint32_t r_[4];                                                   \
            ldsm4(r_, bBase + (uint32_t)u_ * 2048 + boff);                    \
            bF[2 * u_][0]     = r_[0];  bF[2 * u_][1]     = r_[1];            \
            bF[2 * u_ + 1][0] = r_[2];  bF[2 * u_ + 1][1] = r_[3];            \
        }                                                                     \
        _Pragma("unroll")                                                     \
        for (int mt_ = 0; mt_ < 4; ++mt_)                                     \
            _Pragma("unroll")                                                 \
            for (int nt_ = 0; nt_ < 4; ++nt_)                                 \
                mma_f16(acc[mt_][nt_], aF[mt_], bF[nt_]);                     \
    } while (0)

    mbar_wait(fullb0, 0);
    unsigned phbits = 1u;
    unsigned eph    = 0u;      // producer-thread parity bits (tid 224)
    int stage = 0;

    for (int c = 0; c < NC; ++c) {
        const uint32_t aBase = sbase + (uint32_t)stage * STAGE_BYTES + aRow * 128;
        const uint32_t bBase = sbase + (uint32_t)stage * STAGE_BYTES + AB_TILE + bRow * 128;

        KSTEP(0);
        KSTEP(1);
        KSTEP(2);

        int snext = stage + 1; if (snext == STAGES) snext = 0;
        if (c + 1 < NC) {
            mbar_wait(fullb0 + 8 * snext, (phbits >> snext) & 1u);
            phbits ^= (1u << snext);
        }

        KSTEP(3);

        __syncwarp();
        if (l == 0) mbar_arrive(emptyb0 + 8 * stage);

        // producer = warp 7 lane 0 (statistically last arriver; warp 0 freed)
        if (tid == 224) {
            const int cn = c + STAGES;
            if (cn < NC) {
                mbar_wait(emptyb0 + 8 * stage, (eph >> stage) & 1u);
                eph ^= (1u << stage);
                fence_async();
                mbar_expect_tx(fullb0 + 8 * stage, STAGE_BYTES);
                tma2d(sbase + stage * STAGE_BYTES,           &tmaA, cn * BK, bm, fullb0 + 8 * stage);
                tma2d(sbase + stage * STAGE_BYTES + AB_TILE, &tmaB, cn * BK, bn, fullb0 + 8 * stage);
            }
        }

        stage = snext;
    }
    #undef KSTEP

    // -------- fused epilogue (residual from fp16 Xh; evict-first stores) -----
    const float one_mb = 1.0f - beta[0];
    const int colB = bn + warpN + 2 * (l & 3);

    float2 br2[4];
    #pragma unroll
    for (int nt = 0; nt < 4; ++nt)
        br2[nt] = *reinterpret_cast<const float2*>(beta_res + colB + nt * 8);

    #pragma unroll
    for (int mt = 0; mt < 4; ++mt) {
        #pragma unroll
        for (int h = 0; h < 2; ++h) {
            const int row = bm + warpM + mt * 16 + (l >> 2) + h * 8;
            const __half* xr = Xh  + (size_t)row * DIM + colB;
            float*       orw = out + (size_t)row * DIM + colB;
            #pragma unroll
            for (int nt = 0; nt < 4; ++nt) {
                const __half2 xh2 = *reinterpret_cast<const __half2*>(xr + nt * 8);
                const float2 xv = __half22float2(xh2);
                const float d0 = acc[mt][nt][h * 2 + 0];
                const float d1 = acc[mt][nt][h * 2 + 1];
                const float o0 = fmaxf(one_mb + d0, 0.0f);
                const float o1 = fmaxf(one_mb + d1, 0.0f);
                const float r0 = fmaxf(1.0f - (br2[nt].x - (xv.x + o0)), 0.0f);
                const float r1 = fmaxf(1.0f - (br2[nt].y - (xv.y + o1)), 0.0f);
                __stcs(reinterpret_cast<float2*>(orw + nt * 8), make_float2(r0, r1));
            }
        }
    }
}

// ------------------------------------------------------------------ host side
typedef CUresult (*EncodeTiledFn)(CUtensorMap*, CUtensorMapDataType, cuuint32_t, void*,
                                  const cuuint64_t*, const cuuint64_t*, const cuuint32_t*,
                                  const cuuint32_t*, CUtensorMapInterleave, CUtensorMapSwizzle,
                                  CUtensorMapL2promotion, CUtensorMapFloatOOBfill);

static void make_map(EncodeTiledFn enc, CUtensorMap* m, void* ptr) {
    cuuint64_t dims[2]    = {DIM, DIM};
    cuuint64_t strides[1] = {(cuuint64_t)DIM * 2};
    cuuint32_t box[2]     = {BK, 128};
    cuuint32_t es[2]      = {1, 1};
    enc(m, CU_TENSOR_MAP_DATA_TYPE_FLOAT16, 2, ptr, dims, strides, box, es,
        CU_TENSOR_MAP_INTERLEAVE_NONE, CU_TENSOR_MAP_SWIZZLE_128B,
        CU_TENSOR_MAP_L2_PROMOTION_L2_256B, CU_TENSOR_MAP_FLOAT_OOB_FILL_NONE);
}

extern "C" void kernel_launch(void* const* d_in, const int* in_sizes, int n_in,
                              void* d_out, int out_size)
{
    const float* X        = (const float*)d_in[0];
    const float* W        = (const float*)d_in[1];
    const float* beta     = (const float*)d_in[2];
    const float* beta_res = (const float*)d_in[3];
    float* out            = (float*)d_out;

    void *pXh = nullptr, *pWh = nullptr;
    cudaGetSymbolAddress(&pXh, g_Xh);
    cudaGetSymbolAddress(&pWh, g_Wh);

    dim3 pgrid(DIM * DIM / (256 * 16), 2);
    to_half2_kernel<<<pgrid, 256>>>(X, W, (__half*)pXh, (__half*)pWh);

    void* encp = nullptr;
    cudaDriverEntryPointQueryResult st;
    cudaGetDriverEntryPointByVersion("cuTensorMapEncodeTiled", &encp, 12000,
                                     cudaEnableDefault, &st);
    EncodeTiledFn enc = (EncodeTiledFn)encp;

    static CUtensorMap mapA, mapB;
    make_map(enc, &mapA, pXh);
    make_map(enc, &mapB, pWh);

    cudaFuncSetAttribute(resfc_mma_f16_v13,
                         cudaFuncAttributeMaxDynamicSharedMemorySize, SMEM_TOTAL);
    dim3 grid(DIM / BN, DIM / BM);
    resfc_mma_f16_v13<<<grid, NT, SMEM_TOTAL>>>(mapA, mapB, (const __half*)pXh,
                                                beta, beta_res, out);
}

// round 17
// speedup vs baseline: 1.0406x; 1.0349x over previous
// mma.sync fp16 fused GEMM+epilogue, v14 = v13 with the chunk loop unrolled by
// STAGES=3: stage indices, tile base addresses and mbarrier parities all become
// compile-time-constant / single-toggle registers (removes the per-chunk
// stage/snext arithmetic and phbits shift/xor chains -> alu 10% target ~7%).
// Protocol identical to v11/v13: barrier-free mbarrier pipeline, TMA loads,
// 64x32 warp tiles, 2 CTAs/SM, producer = warp 7, evict-first stores.
//   out = relu(1 - beta + X@W^T); res = relu(1 - beta_res + x + out); leaky==id.

#include <cuda_runtime.h>
#include <cuda.h>
#include <cuda_fp16.h>
#include <cstdint>

#define DIM     4096
#define BM      128
#define BN      128
#define BK      64
#define STAGES  3
#define NT      256
#define NC      (DIM / BK)                 // 64
#define AB_TILE (BM * BK * 2)              // 16384
#define STAGE_BYTES (2 * AB_TILE)          // 32768
#define SMEM_MAIN   (STAGES * STAGE_BYTES) // 98304
#define SMEM_TOTAL  (SMEM_MAIN + 64)       // full[0..2] @ +0, empty[0..2] @ +24

// ------------------------------------------------------------------ scratch
__device__ __half g_Xh[(size_t)DIM * DIM];
__device__ __half g_Wh[(size_t)DIM * DIM];

// ------------------------------------------------------------------ helpers
__device__ __forceinline__ uint32_t smem_u32(const void* p) {
    uint32_t a;
    asm("{ .reg .u64 t; cvta.to.shared.u64 t, %1; cvt.u32.u64 %0, t; }" : "=r"(a) : "l"(p));
    return a;
}
__device__ __forceinline__ void mbar_init(uint32_t m, uint32_t cnt) {
    asm volatile("mbarrier.init.shared.b64 [%0], %1;" :: "r"(m), "r"(cnt) : "memory");
}
__device__ __forceinline__ void mbar_arrive(uint32_t m) {
    asm volatile("mbarrier.arrive.shared.b64 _, [%0];" :: "r"(m) : "memory");
}
__device__ __forceinline__ void mbar_expect_tx(uint32_t m, uint32_t bytes) {
    asm volatile("mbarrier.arrive.expect_tx.shared.b64 _, [%0], %1;"
                 :: "r"(m), "r"(bytes) : "memory");
}
__device__ __forceinline__ void mbar_wait(uint32_t m, uint32_t parity) {
    asm volatile(
        "{\n\t.reg .pred P;\n\t"
        "WL_%=:\n\t"
        "mbarrier.try_wait.parity.acquire.cta.shared::cta.b64 P, [%0], %1, 0x989680;\n\t"
        "@!P bra.uni WL_%=;\n\t}"
        :: "r"(m), "r"(parity) : "memory");
}
__device__ __forceinline__ void fence_async() {
    asm volatile("fence.proxy.async.shared::cta;" ::: "memory");
}
__device__ __forceinline__ void tma2d(uint32_t dst, const CUtensorMap* map,
                                      int x, int y, uint32_t bar) {
    asm volatile(
        "cp.async.bulk.tensor.2d.shared::cta.global.tile.mbarrier::complete_tx::bytes "
        "[%0], [%1, {%2, %3}], [%4];"
        :: "r"(dst), "l"(map), "r"(x), "r"(y), "r"(bar) : "memory");
}
__device__ __forceinline__ void ldsm4(uint32_t* r, uint32_t addr) {
    asm volatile("ldmatrix.sync.aligned.m8n8.x4.shared.b16 {%0,%1,%2,%3}, [%4];"
                 : "=r"(r[0]), "=r"(r[1]), "=r"(r[2]), "=r"(r[3]) : "r"(addr));
}
__device__ __forceinline__ void mma_f16(float* d, const uint32_t* a, const uint32_t* b) {
    asm volatile(
        "mma.sync.aligned.m16n8k16.row.col.f32.f16.f16.f32 "
        "{%0,%1,%2,%3}, {%4,%5,%6,%7}, {%8,%9}, {%0,%1,%2,%3};"
        : "+f"(d[0]), "+f"(d[1]), "+f"(d[2]), "+f"(d[3])
        : "r"(a[0]), "r"(a[1]), "r"(a[2]), "r"(a[3]), "r"(b[0]), "r"(b[1]));
}

// ------------------------------------------------------------------ prep kernel
// 16 floats -> 16 halves per thread (MLP 4) — measured best.
__global__ void __launch_bounds__(256) to_half2_kernel(const float* __restrict__ x,
                                                       const float* __restrict__ w,
                                                       __half* __restrict__ xh,
                                                       __half* __restrict__ wh) {
    const float* in  = blockIdx.y ? w : x;
    __half* outp     = blockIdx.y ? wh : xh;
    size_t i = ((size_t)blockIdx.x * blockDim.x + threadIdx.x) * 16;
    float4 v0 = __ldcs(reinterpret_cast<const float4*>(in + i));
    float4 v1 = __ldcs(reinterpret_cast<const float4*>(in + i + 4));
    float4 v2 = __ldcs(reinterpret_cast<const float4*>(in + i + 8));
    float4 v3 = __ldcs(reinterpret_cast<const float4*>(in + i + 12));
    __half2 h0 = __floats2half2_rn(v0.x, v0.y);
    __half2 h1 = __floats2half2_rn(v0.z, v0.w);
    __half2 h2 = __floats2half2_rn(v1.x, v1.y);
    __half2 h3 = __floats2half2_rn(v1.z, v1.w);
    __half2 h4 = __floats2half2_rn(v2.x, v2.y);
    __half2 h5 = __floats2half2_rn(v2.z, v2.w);
    __half2 h6 = __floats2half2_rn(v3.x, v3.y);
    __half2 h7 = __floats2half2_rn(v3.z, v3.w);
    uint4 o0, o1;
    o0.x = *reinterpret_cast<uint32_t*>(&h0);
    o0.y = *reinterpret_cast<uint32_t*>(&h1);
    o0.z = *reinterpret_cast<uint32_t*>(&h2);
    o0.w = *reinterpret_cast<uint32_t*>(&h3);
    o1.x = *reinterpret_cast<uint32_t*>(&h4);
    o1.y = *reinterpret_cast<uint32_t*>(&h5);
    o1.z = *reinterpret_cast<uint32_t*>(&h6);
    o1.w = *reinterpret_cast<uint32_t*>(&h7);
    *reinterpret_cast<uint4*>(outp + i)     = o0;
    *reinterpret_cast<uint4*>(outp + i + 8) = o1;
}

// ------------------------------------------------------------------ main kernel
__global__ void __launch_bounds__(NT, 2)
resfc_mma_f16_v14(const __grid_constant__ CUtensorMap tmaA,
                  const __grid_constant__ CUtensorMap tmaB,
                  const __half* __restrict__ Xh,
                  const float* __restrict__ beta,
                  const float* __restrict__ beta_res,
                  float* __restrict__ out)
{
    extern __shared__ __align__(1024) char smem[];
    const uint32_t sbase = smem_u32(smem);
    const uint32_t fullb0  = sbase + SMEM_MAIN;
    const uint32_t emptyb0 = sbase + SMEM_MAIN + 24;
    const int tid = threadIdx.x;
    const int l   = tid & 31;
    const int wid = tid >> 5;
    const int warpM = (wid & 1) * 64;
    const int warpN = (wid >> 1) * 32;
    const int bm = blockIdx.y * BM;
    const int bn = blockIdx.x * BN;

    if (tid == 0) {
        #pragma unroll
        for (int s = 0; s < STAGES; ++s) {
            mbar_init(fullb0  + 8 * s, 1);
            mbar_init(emptyb0 + 8 * s, 8);
        }
    }
    __syncthreads();

    // prologue: chunks 0,1,2 -> stages 0,1,2
    if (tid == 0) {
        #pragma unroll
        for (int s = 0; s < STAGES; ++s) {
            mbar_expect_tx(fullb0 + 8 * s, STAGE_BYTES);
            tma2d(sbase + s * STAGE_BYTES,           &tmaA, s * BK, bm, fullb0 + 8 * s);
            tma2d(sbase + s * STAGE_BYTES + AB_TILE, &tmaB, s * BK, bn, fullb0 + 8 * s);
        }
    }

    const uint32_t xorv   = (uint32_t)(l & 7) << 4;
    const uint32_t aRow   = (uint32_t)(warpM + (l & 15));
    const uint32_t aByteH = (uint32_t)(l & 16);
    const uint32_t bRow   = (uint32_t)(warpN + (l & 7) + ((l >> 1) & 8));
    const uint32_t bByteH = (uint32_t)((l & 8) << 1);

    // loop-invariant per-stage tile bases (6 registers, computed once)
    const uint32_t aB0 = sbase + 0 * STAGE_BYTES + aRow * 128;
    const uint32_t aB1 = sbase + 1 * STAGE_BYTES + aRow * 128;
    const uint32_t aB2 = sbase + 2 * STAGE_BYTES + aRow * 128;
    const uint32_t bB0 = sbase + 0 * STAGE_BYTES + AB_TILE + bRow * 128;
    const uint32_t bB1 = sbase + 1 * STAGE_BYTES + AB_TILE + bRow * 128;
    const uint32_t bB2 = sbase + 2 * STAGE_BYTES + AB_TILE + bRow * 128;

    float acc[4][4][4];
    #pragma unroll
    for (int i = 0; i < 4; ++i)
        #pragma unroll
        for (int j = 0; j < 4; ++j)
            #pragma unroll
            for (int k = 0; k < 4; ++k)
                acc[i][j][k] = 0.0f;

    #define KSTEP(s, aBase, bBase) do {                                       \
        uint32_t aF[4][4];                                                    \
        uint32_t bF[4][2];                                                    \
        const uint32_t aoff = ((uint32_t)((s) * 32) + aByteH) ^ xorv;         \
        const uint32_t boff = ((uint32_t)((s) * 32) + bByteH) ^ xorv;         \
        _Pragma("unroll")                                                     \
        for (int t_ = 0; t_ < 4; ++t_)                                        \
            ldsm4(aF[t_], (aBase) + (uint32_t)t_ * 2048 + aoff);              \
        _Pragma("unroll")                                                     \
        for (int u_ = 0; u_ < 2; ++u_) {                                      \
            uint32_t r_[4];                                                   \
            ldsm4(r_, (bBase) + (uint32_t)u_ * 2048 + boff);                  \
            bF[2 * u_][0]     = r_[0];  bF[2 * u_][1]     = r_[1];            \
            bF[2 * u_ + 1][0] = r_[2];  bF[2 * u_ + 1][1] = r_[3];            \
        }                                                                     \
        _Pragma("unroll")                                                     \
        for (int mt_ = 0; mt_ < 4; ++mt_)                                     \
            _Pragma("unroll")                                                 \
            for (int nt_ = 0; nt_ < 4; ++nt_)                                 \
                mma_f16(acc[mt_][nt_], aF[mt_], bF[nt_]);                     \
    } while (0)

    // One unrolled slot: chunk c at stage S; waits full[NS] for chunk c+1
    // (parity pN, toggled); producer refills stage S with chunk c+3.
    #define SLOT(S, NS, aBase, bBase, pN, eS, cIssue, doIssue) do {            \
        KSTEP(0, aBase, bBase);                                                \
        KSTEP(1, aBase, bBase);                                                \
        KSTEP(2, aBase, bBase);                                                \
        mbar_wait(fullb0 + 8 * (NS), (pN));  (pN) ^= 1u;                       \
        KSTEP(3, aBase, bBase);                                                \
        __syncwarp();                                                          \
        if (l == 0) mbar_arrive(emptyb0 + 8 * (S));                            \
        if (tid == 224 && (doIssue)) {                                         \
            mbar_wait(emptyb0 + 8 * (S), (eS));  (eS) ^= 1u;                   \
            fence_async();                                                     \
            mbar_expect_tx(fullb0 + 8 * (S), STAGE_BYTES);                     \
            tma2d(sbase + (S) * STAGE_BYTES,           &tmaA, (cIssue) * BK, bm, fullb0 + 8 * (S)); \
            tma2d(sbase + (S) * STAGE_BYTES + AB_TILE, &tmaB, (cIssue) * BK, bn, fullb0 + 8 * (S)); \
        }                                                                      \
    } while (0)

    // wait for chunk 0 (stage 0) before the loop
    mbar_wait(fullb0, 0);
    uint32_t p0 = 1u, p1 = 0u, p2 = 0u;          // full-barrier parities
    uint32_t e0 = 0u, e1 = 0u, e2 = 0u;          // empty parities (tid 224)

    for (int g = 0; g < 21; ++g) {               // chunks 3g, 3g+1, 3g+2
        const int c = 3 * g;
        SLOT(0, 1, aB0, bB0, p1, e0, c + 3, true);      // c+3 <= 63 always
        SLOT(1, 2, aB1, bB1, p2, e1, c + 4, g != 20);   // skip at g=20 (c+4=64)
        SLOT(2, 0, aB2, bB2, p0, e2, c + 5, g != 20);   // skip at g=20 (c+5=65)
    }
    // peeled remainder: chunk 63, stage 0 (full[0] already waited in g=20 slot2)
    KSTEP(0, aB0, bB0);
    KSTEP(1, aB0, bB0);
    KSTEP(2, aB0, bB0);
    KSTEP(3, aB0, bB0);
    #undef SLOT
    #undef KSTEP

    // -------- fused epilogue (residual from fp16 Xh; evict-first stores) -----
    const float one_mb = 1.0f - beta[0];
    const int colB = bn + warpN + 2 * (l & 3);

    float2 br2[4];
    #pragma unroll
    for (int nt = 0; nt < 4; ++nt)
        br2[nt] = *reinterpret_cast<const float2*>(beta_res + colB + nt * 8);

    #pragma unroll
    for (int mt = 0; mt < 4; ++mt) {
        #pragma unroll
        for (int h = 0; h < 2; ++h) {
            const int row = bm + warpM + mt * 16 + (l >> 2) + h * 8;
            const __half* xr = Xh  + (size_t)row * DIM + colB;
            float*       orw = out + (size_t)row * DIM + colB;
            #pragma unroll
            for (int nt = 0; nt < 4; ++nt) {
                const __half2 xh2 = *reinterpret_cast<const __half2*>(xr + nt * 8);
                const float2 xv = __half22float2(xh2);
                const float d0 = acc[mt][nt][h * 2 + 0];
                const float d1 = acc[mt][nt][h * 2 + 1];
                const float o0 = fmaxf(one_mb + d0, 0.0f);
                const float o1 = fmaxf(one_mb + d1, 0.0f);
                const float r0 = fmaxf(1.0f - (br2[nt].x - (xv.x + o0)), 0.0f);
                const float r1 = fmaxf(1.0f - (br2[nt].y - (xv.y + o1)), 0.0f);
                __stcs(reinterpret_cast<float2*>(orw + nt * 8), make_float2(r0, r1));
            }
        }
    }
}

// ------------------------------------------------------------------ host side
typedef CUresult (*EncodeTiledFn)(CUtensorMap*, CUtensorMapDataType, cuuint32_t, void*,
                                  const cuuint64_t*, const cuuint64_t*, const cuuint32_t*,
                                  const cuuint32_t*, CUtensorMapInterleave, CUtensorMapSwizzle,
                                  CUtensorMapL2promotion, CUtensorMapFloatOOBfill);

static void make_map(EncodeTiledFn enc, CUtensorMap* m, void* ptr) {
    cuuint64_t dims[2]    = {DIM, DIM};
    cuuint64_t strides[1] = {(cuuint64_t)DIM * 2};
    cuuint32_t box[2]     = {BK, 128};
    cuuint32_t es[2]      = {1, 1};
    enc(m, CU_TENSOR_MAP_DATA_TYPE_FLOAT16, 2, ptr, dims, strides, box, es,
        CU_TENSOR_MAP_INTERLEAVE_NONE, CU_TENSOR_MAP_SWIZZLE_128B,
        CU_TENSOR_MAP_L2_PROMOTION_L2_256B, CU_TENSOR_MAP_FLOAT_OOB_FILL_NONE);
}

extern "C" void kernel_launch(void* const* d_in, const int* in_sizes, int n_in,
                              void* d_out, int out_size)
{
    const float* X        = (const float*)d_in[0];
    const float* W        = (const float*)d_in[1];
    const float* beta     = (const float*)d_in[2];
    const float* beta_res = (const float*)d_in[3];
    float* out            = (float*)d_out;

    void *pXh = nullptr, *pWh = nullptr;
    cudaGetSymbolAddress(&pXh, g_Xh);
    cudaGetSymbolAddress(&pWh, g_Wh);

    dim3 pgrid(DIM * DIM / (256 * 16), 2);
    to_half2_kernel<<<pgrid, 256>>>(X, W, (__half*)pXh, (__half*)pWh);

    void* encp = nullptr;
    cudaDriverEntryPointQueryResult st;
    cudaGetDriverEntryPointByVersion("cuTensorMapEncodeTiled", &encp, 12000,
                                     cudaEnableDefault, &st);
    EncodeTiledFn enc = (EncodeTiledFn)encp;

    static CUtensorMap mapA, mapB;
    make_map(enc, &mapA, pXh);
    make_map(enc, &mapB, pWh);

    cudaFuncSetAttribute(resfc_mma_f16_v14,
                         cudaFuncAttributeMaxDynamicSharedMemorySize, SMEM_TOTAL);
    dim3 grid(DIM / BN, DIM / BM);
    resfc_mma_f16_v14<<<grid, NT, SMEM_TOTAL>>>(mapA, mapB, (const __half*)pXh,
                                                beta, beta_res, out);
}